// round 5
// baseline (speedup 1.0000x reference)
#include <cuda_runtime.h>
#include <cstdint>

constexpr int Bc = 32;
constexpr int Hc = 512;
constexpr int Wc = 512;
constexpr int Pc = 100000;
constexpr long long Nc = (long long)Bc * Pc;   // 3,200,000 points
constexpr int BDIM = 256;
constexpr int PPT  = 4;                        // points per thread
constexpr int NBLK = (int)(Nc / ((long long)BDIM * PPT));  // 3125 blocks
static_assert(Nc % ((long long)BDIM * PPT) == 0, "grid must tile exactly");
static_assert(Pc % PPT == 0, "4 consecutive points always share a batch index");

__device__ float    g_partial[NBLK];
__device__ unsigned g_count = 0;   // returns to 0 at the end of every launch

__device__ __forceinline__ float point_loss(float zA, float zB, int o) {
    float d  = zA - zB;
    float gt = (float)o - 1.0f;          // in {-1, 0, +1}
    float sm = log1pf(expf(-gt * d));    // soft-margin branch (gt = +/-1)
    return (o == 1) ? (d * d) : sm;
}

__global__ __launch_bounds__(BDIM)
void loss_kernel(const float* __restrict__ img,
                 const int* __restrict__ xA,
                 const int* __restrict__ yA,
                 const int* __restrict__ xB,
                 const int* __restrict__ yB,
                 const int* __restrict__ ord,
                 float* __restrict__ out)
{
    const long long base = ((long long)blockIdx.x * BDIM + threadIdx.x) * PPT;

    // 4 consecutive points: same batch (P % 4 == 0, base % 4 == 0)
    const int b = (int)(base / Pc);
    const float* __restrict__ imgb = img + (long long)b * (Hc * Wc);

    // 128-bit vector loads of all five int32 streams
    int4 xa = *reinterpret_cast<const int4*>(xA + base);
    int4 ya = *reinterpret_cast<const int4*>(yA + base);
    int4 xb = *reinterpret_cast<const int4*>(xB + base);
    int4 yb = *reinterpret_cast<const int4*>(yB + base);
    int4 o4 = *reinterpret_cast<const int4*>(ord + base);

    // Offsets: y*512 + x
    unsigned offA0 = ((unsigned)ya.x << 9) | (unsigned)xa.x;
    unsigned offA1 = ((unsigned)ya.y << 9) | (unsigned)xa.y;
    unsigned offA2 = ((unsigned)ya.z << 9) | (unsigned)xa.z;
    unsigned offA3 = ((unsigned)ya.w << 9) | (unsigned)xa.w;
    unsigned offB0 = ((unsigned)yb.x << 9) | (unsigned)xb.x;
    unsigned offB1 = ((unsigned)yb.y << 9) | (unsigned)xb.y;
    unsigned offB2 = ((unsigned)yb.z << 9) | (unsigned)xb.z;
    unsigned offB3 = ((unsigned)yb.w << 9) | (unsigned)xb.w;

    // Issue all 8 gathers before consuming (MLP)
    float zA0 = __ldg(imgb + offA0);
    float zA1 = __ldg(imgb + offA1);
    float zA2 = __ldg(imgb + offA2);
    float zA3 = __ldg(imgb + offA3);
    float zB0 = __ldg(imgb + offB0);
    float zB1 = __ldg(imgb + offB1);
    float zB2 = __ldg(imgb + offB2);
    float zB3 = __ldg(imgb + offB3);

    float s = point_loss(zA0, zB0, o4.x)
            + point_loss(zA1, zB1, o4.y)
            + point_loss(zA2, zB2, o4.z)
            + point_loss(zA3, zB3, o4.w);

    // Warp reduce
    #pragma unroll
    for (int off = 16; off > 0; off >>= 1)
        s += __shfl_xor_sync(0xFFFFFFFFu, s, off);

    __shared__ float warp_sums[BDIM / 32];
    int lane = threadIdx.x & 31;
    int wid  = threadIdx.x >> 5;
    if (lane == 0) warp_sums[wid] = s;
    __syncthreads();

    // Warps 1..7 are done — they exit here, freeing scheduler slots.
    if (wid != 0) return;

    // Warp 0 finishes the block sum and runs the tail protocol alone.
    float v = (lane < BDIM / 32) ? warp_sums[lane] : 0.0f;
    #pragma unroll
    for (int off = 4; off > 0; off >>= 1)
        v += __shfl_xor_sync(0xFFFFFFFFu, v, off);

    unsigned prev = 0;
    if (lane == 0) {
        g_partial[blockIdx.x] = v;
        // release-scope atomic: orders the g_partial store without a full membar
        asm volatile("atom.add.release.gpu.global.u32 %0, [%1], %2;"
                     : "=r"(prev)
                     : "l"(&g_count), "r"(1u)
                     : "memory");
    }
    prev = __shfl_sync(0xFFFFFFFFu, prev, 0);
    if (prev != (unsigned)(NBLK - 1)) return;

    // Last arriving block: warp 0 reduces all partials (deterministic order).
    // acquire fence so all g_partial stores are visible
    asm volatile("fence.acquire.gpu;" ::: "memory");

    float t = 0.0f;
    #pragma unroll 4
    for (int i = lane; i < NBLK; i += 32)
        t += g_partial[i];

    #pragma unroll
    for (int off = 16; off > 0; off >>= 1)
        t += __shfl_xor_sync(0xFFFFFFFFu, t, off);

    if (lane == 0) {
        out[0] = t * (1.0f / (float)Nc);
        g_count = 0;               // reset for next graph replay
    }
}

extern "C" void kernel_launch(void* const* d_in, const int* in_sizes, int n_in,
                              void* d_out, int out_size)
{
    const float* img = (const float*)d_in[0];
    const int*   xA  = (const int*)d_in[1];
    const int*   yA  = (const int*)d_in[2];
    const int*   xB  = (const int*)d_in[3];
    const int*   yB  = (const int*)d_in[4];
    const int*   ord = (const int*)d_in[5];
    float* out = (float*)d_out;

    loss_kernel<<<NBLK, BDIM>>>(img, xA, yA, xB, yB, ord, out);
}

// round 6
// speedup vs baseline: 1.3167x; 1.3167x over previous
#include <cuda_runtime.h>
#include <cstdint>

constexpr int Bc = 32;
constexpr int Hc = 512;
constexpr int Wc = 512;
constexpr int Pc = 100000;
constexpr long long Nc = (long long)Bc * Pc;   // 3,200,000 points
constexpr int BDIM = 256;
constexpr int PPT  = 4;                        // points per thread
constexpr int NBLK = (int)(Nc / ((long long)BDIM * PPT));  // 3125 blocks
static_assert(Nc % ((long long)BDIM * PPT) == 0, "grid must tile exactly");
static_assert(Pc % PPT == 0, "4 consecutive points always share a batch index");

__device__ float g_sum = 0.0f;   // reset by epilogue every launch

__device__ __forceinline__ float point_loss(float zA, float zB, int o) {
    float d  = zA - zB;
    float gt = (float)o - 1.0f;          // in {-1, 0, +1}
    float sm = log1pf(expf(-gt * d));    // soft-margin branch (gt = +/-1)
    return (o == 1) ? (d * d) : sm;
}

__device__ __forceinline__ int4 ldcs4(const int* p) {
    return __ldcs(reinterpret_cast<const int4*>(p));
}

__global__ __launch_bounds__(BDIM)
void loss_kernel(const float* __restrict__ img,
                 const int* __restrict__ xA,
                 const int* __restrict__ yA,
                 const int* __restrict__ xB,
                 const int* __restrict__ yB,
                 const int* __restrict__ ord)
{
    const long long base = ((long long)blockIdx.x * BDIM + threadIdx.x) * PPT;

    // 4 consecutive points: same batch (P % 4 == 0, base % 4 == 0)
    const int b = (int)(base / Pc);
    const float* __restrict__ imgb = img + (long long)b * (Hc * Wc);

    // 128-bit evict-first streaming loads of all five int32 streams
    // (keeps the 33.5MB image resident in L2 across graph replays)
    int4 xa = ldcs4(xA + base);
    int4 ya = ldcs4(yA + base);
    int4 xb = ldcs4(xB + base);
    int4 yb = ldcs4(yB + base);
    int4 o4 = ldcs4(ord + base);

    // Offsets: y*512 + x
    unsigned offA0 = ((unsigned)ya.x << 9) | (unsigned)xa.x;
    unsigned offA1 = ((unsigned)ya.y << 9) | (unsigned)xa.y;
    unsigned offA2 = ((unsigned)ya.z << 9) | (unsigned)xa.z;
    unsigned offA3 = ((unsigned)ya.w << 9) | (unsigned)xa.w;
    unsigned offB0 = ((unsigned)yb.x << 9) | (unsigned)xb.x;
    unsigned offB1 = ((unsigned)yb.y << 9) | (unsigned)xb.y;
    unsigned offB2 = ((unsigned)yb.z << 9) | (unsigned)xb.z;
    unsigned offB3 = ((unsigned)yb.w << 9) | (unsigned)xb.w;

    // Issue all 8 gathers before consuming (MLP)
    float zA0 = __ldg(imgb + offA0);
    float zA1 = __ldg(imgb + offA1);
    float zA2 = __ldg(imgb + offA2);
    float zA3 = __ldg(imgb + offA3);
    float zB0 = __ldg(imgb + offB0);
    float zB1 = __ldg(imgb + offB1);
    float zB2 = __ldg(imgb + offB2);
    float zB3 = __ldg(imgb + offB3);

    float s = point_loss(zA0, zB0, o4.x)
            + point_loss(zA1, zB1, o4.y)
            + point_loss(zA2, zB2, o4.z)
            + point_loss(zA3, zB3, o4.w);

    // Warp reduce
    #pragma unroll
    for (int off = 16; off > 0; off >>= 1)
        s += __shfl_xor_sync(0xFFFFFFFFu, s, off);

    __shared__ float warp_sums[BDIM / 32];
    int lane = threadIdx.x & 31;
    int wid  = threadIdx.x >> 5;
    if (lane == 0) warp_sums[wid] = s;
    __syncthreads();

    if (threadIdx.x == 0) {
        float v = warp_sums[0];
        #pragma unroll
        for (int w = 1; w < BDIM / 32; w++) v += warp_sums[w];
        // Fire-and-forget reduction: result unused -> RED.E.ADD.F32,
        // no return-trip latency, no fence, CTA retires immediately.
        atomicAdd(&g_sum, v);
    }
}

__global__ void epilogue_kernel(float* __restrict__ out)
{
    if (threadIdx.x == 0) {
        out[0] = g_sum * (1.0f / (float)Nc);
        g_sum = 0.0f;              // reset for next graph replay
    }
}

extern "C" void kernel_launch(void* const* d_in, const int* in_sizes, int n_in,
                              void* d_out, int out_size)
{
    const float* img = (const float*)d_in[0];
    const int*   xA  = (const int*)d_in[1];
    const int*   yA  = (const int*)d_in[2];
    const int*   xB  = (const int*)d_in[3];
    const int*   yB  = (const int*)d_in[4];
    const int*   ord = (const int*)d_in[5];
    float* out = (float*)d_out;

    loss_kernel<<<NBLK, BDIM>>>(img, xA, yA, xB, yB, ord);
    epilogue_kernel<<<1, 32>>>(out);
}